// round 3
// baseline (speedup 1.0000x reference)
#include <cuda_runtime.h>
#include <cstdint>

// HGN forward, fused. Shapes fixed by problem: U=I=100000, D=64, L=50, B=4096, T=100.
#define D 64
#define LSEQ 50
#define TPRED 100
#define BPB 4        // batches per block in main kernel (amortizes fg_item_W column load)
#define PRE_BPB 16   // batches per block in precompute kernel
#define BMAX 4096

// Scratch (static device arrays — no allocation allowed)
__device__ float g_ubias[BMAX * D];    // (u @ fg_user_W) + fg_user_b + fg_item_b
__device__ float g_ugu[BMAX * LSEQ];   // u @ instance_gate_user

static __device__ __forceinline__ unsigned long long pk(float a, float b) {
    unsigned long long r;
    asm("mov.b64 %0, {%1, %2};" : "=l"(r) : "f"(a), "f"(b));
    return r;
}
static __device__ __forceinline__ void upk(unsigned long long v, float& a, float& b) {
    asm("mov.b64 {%0, %1}, %2;" : "=f"(a), "=f"(b) : "l"(v));
}
static __device__ __forceinline__ unsigned long long fma2(
    unsigned long long a, unsigned long long b, unsigned long long c) {
    unsigned long long r;
    asm("fma.rn.f32x2 %0, %1, %2, %3;" : "=l"(r) : "l"(a), "l"(b), "l"(c));
    return r;
}
static __device__ __forceinline__ float sigmoidf(float x) {
    return 1.0f / (1.0f + __expf(-x));
}

// ---------------------------------------------------------------------------
// Precompute kernel: for every batch b,
//   g_ubias[b][d] = sum_k u[k]*fg_user_W[k][d] + fg_user_b[d] + fg_item_b[d]
//   g_ugu[b][l]   = sum_k u[k]*instance_gate_user[k][l]
// Weight columns are register-cached per thread; user vector broadcast via SMEM.
// ---------------------------------------------------------------------------
__global__ __launch_bounds__(128) void hgn_pre(
    const int* __restrict__ user_ids,
    const float* __restrict__ user_tab,
    const float* __restrict__ fuW,
    const float* __restrict__ fub,
    const float* __restrict__ fib,
    const float* __restrict__ gu,
    int B)
{
    __shared__ __align__(16) float s_u[D];
    const int j = threadIdx.x;   // output column: j<64 -> ubias, 64<=j<114 -> ugu

    float wcol[D];
    float biasj = 0.0f;
    if (j < D) {
        #pragma unroll
        for (int k = 0; k < D; k++) wcol[k] = fuW[k * D + j];
        biasj = fub[j] + fib[j];
    } else if (j < D + LSEQ) {
        const int jj = j - D;
        #pragma unroll
        for (int k = 0; k < D; k++) wcol[k] = gu[k * LSEQ + jj];
    }

    const int b0 = blockIdx.x * PRE_BPB;
    for (int bb = 0; bb < PRE_BPB; bb++) {
        const int b = b0 + bb;
        if (b >= B) break;
        if (j < D) {
            const int uid = user_ids[b];
            s_u[j] = user_tab[(size_t)uid * D + j];
        }
        __syncthreads();
        float acc = biasj;
        const float4* up = (const float4*)s_u;
        #pragma unroll
        for (int q = 0; q < D / 4; q++) {
            float4 r = up[q];
            acc += r.x * wcol[4 * q + 0] + r.y * wcol[4 * q + 1]
                 + r.z * wcol[4 * q + 2] + r.w * wcol[4 * q + 3];
        }
        if (j < D)            g_ubias[b * D + j] = acc;
        else if (j < D + LSEQ) g_ugu[b * LSEQ + (j - D)] = acc;
        __syncthreads();
    }
}

// ---------------------------------------------------------------------------
// Main kernel: one block (64 threads = 2 warps) handles BPB batches.
// Per batch: gather item embs -> gating matmul (f32x2 packed) -> instance
// gating -> union vector v -> fused scoring over T=100 gathered W2 rows.
// ---------------------------------------------------------------------------
__global__ __launch_bounds__(64) void hgn_main(
    const int* __restrict__ item_seq,
    const int* __restrict__ user_ids,
    const int* __restrict__ items_pred,
    const float* __restrict__ user_tab,
    const float* __restrict__ item_tab,
    const float* __restrict__ fiW,
    const float* __restrict__ gi,
    const float* __restrict__ W2,
    const float* __restrict__ b2,
    float* __restrict__ out,
    int B)
{
    __shared__ __align__(16) float s_item[LSEQ][D];
    __shared__ __align__(16) float s_gated[LSEQ][D];
    __shared__ __align__(16) float s_v[D];
    __shared__ float s_score[LSEQ];
    __shared__ int s_idx[TPRED];
    __shared__ int s_seq[LSEQ];

    const int d    = threadIdx.x;       // 0..63 = feature dim
    const int lane = d & 31;
    const int warp = d >> 5;

    // fg_item_W column d, packed as 32 f32x2 values (register-resident, reused
    // for all BPB batches).
    unsigned long long colp[D / 2];
    #pragma unroll
    for (int k = 0; k < D / 2; k++) {
        float a = fiW[(2 * k) * D + d];
        float c = fiW[(2 * k + 1) * D + d];
        colp[k] = pk(a, c);
    }
    const float gi_lo = gi[lane];
    const float gi_hi = gi[lane + 32];

    for (int bb = 0; bb < BPB; bb++) {
        const int b = blockIdx.x * BPB + bb;
        if (b >= B) break;

        // --- stage indices into SMEM ---
        s_idx[d] = items_pred[b * TPRED + d];
        if (d < TPRED - D) s_idx[D + d] = items_pred[b * TPRED + D + d];
        if (d < LSEQ) s_seq[d] = item_seq[b * LSEQ + d];
        __syncthreads();

        // --- user embedding + precomputed gate bias ---
        const int uid = user_ids[b];
        const float u = user_tab[(size_t)uid * D + d];
        const float bias = g_ubias[b * D + d];

        // --- gather item embeddings (coalesced 256B rows), running sum ---
        float isum = 0.0f;
        #pragma unroll 5
        for (int l = 0; l < LSEQ; l++) {
            float val = item_tab[(size_t)s_seq[l] * D + d];
            s_item[l][d] = val;
            isum += val;
        }
        __syncthreads();

        // --- feature gating: logit[l][d] = bias[d] + item[l][:] . fiW[:,d] ---
        for (int l = 0; l < LSEQ; l++) {
            unsigned long long acc0 = pk(bias, 0.0f);
            unsigned long long acc1 = pk(0.0f, 0.0f);
            const float4* row = (const float4*)s_item[l];
            #pragma unroll
            for (int q = 0; q < D / 4; q++) {
                float4 r = row[q];
                acc0 = fma2(pk(r.x, r.y), colp[2 * q + 0], acc0);
                acc1 = fma2(pk(r.z, r.w), colp[2 * q + 1], acc1);
            }
            float a0, a1, a2, a3;
            upk(acc0, a0, a1);
            upk(acc1, a2, a3);
            const float logit = (a0 + a1) + (a2 + a3);
            s_gated[l][d] = s_item[l][d] * sigmoidf(logit);
        }
        __syncthreads();

        // --- instance gating: score[l] = sigmoid(gated[l].gi + u.gu[:,l]) ---
        for (int l = warp; l < LSEQ; l += 2) {
            float p = s_gated[l][lane] * gi_lo + s_gated[l][lane + 32] * gi_hi;
            p += __shfl_xor_sync(0xffffffffu, p, 16);
            p += __shfl_xor_sync(0xffffffffu, p, 8);
            p += __shfl_xor_sync(0xffffffffu, p, 4);
            p += __shfl_xor_sync(0xffffffffu, p, 2);
            p += __shfl_xor_sync(0xffffffffu, p, 1);
            if (lane == 0) {
                s_score[l] = sigmoidf(p + g_ugu[b * LSEQ + l]);
            }
        }
        __syncthreads();

        // --- union vector: v = u + sum_l(item) + sum_l(gated*score)/sum(score)
        float ssum = 0.0f, uo = 0.0f;
        #pragma unroll 5
        for (int l = 0; l < LSEQ; l++) {
            const float sc = s_score[l];
            ssum += sc;
            uo += s_gated[l][d] * sc;
        }
        s_v[d] = u + isum + uo / ssum;
        __syncthreads();

        // --- scoring: res[t] = b2[it] + W2[it] . v  (4 outputs per warp/iter,
        //     8-lane groups, coalesced 128B row segments) ---
        const int g4 = lane >> 3;   // which of 4 outputs this lane serves
        const int gl = lane & 7;    // position within the 8-lane group
        const float4 va = *(const float4*)&s_v[gl * 8];
        const float4 vb = *(const float4*)&s_v[gl * 8 + 4];
        float* outp = out + (size_t)b * TPRED;
        #pragma unroll
        for (int i = 0; i < 13; i++) {
            const int t = warp * 4 + g4 + 8 * i;
            const int tt = (t < TPRED) ? t : 0;
            const int it = s_idx[tt];
            const float4* rowp = (const float4*)(W2 + (size_t)it * D);
            const float4 a = rowp[gl * 2];
            const float4 c = rowp[gl * 2 + 1];
            float p = a.x * va.x + a.y * va.y + a.z * va.z + a.w * va.w
                    + c.x * vb.x + c.y * vb.y + c.z * vb.z + c.w * vb.w;
            p += __shfl_xor_sync(0xffffffffu, p, 1);
            p += __shfl_xor_sync(0xffffffffu, p, 2);
            p += __shfl_xor_sync(0xffffffffu, p, 4);
            if (t < TPRED && gl == 0) outp[t] = p + b2[it];
        }
        __syncthreads();   // smem reuse for next batch
    }
}

// ---------------------------------------------------------------------------
// Harness entry. Inputs (metadata order):
//  0 item_seq[B,L] i32   1 user_ids[B] i32      2 items_to_predict[B,T] i32
//  3 user_emb[U,D] f32   4 item_emb[I,D] f32
//  5 fg_item_W[D,D]      6 fg_item_b[D]         7 fg_user_W[D,D]   8 fg_user_b[D]
//  9 instance_gate_item[D,1]  10 instance_gate_user[D,L]
// 11 W2_table[I,D]      12 b2_table[I,1]
// Output: res[B,T] f32
// ---------------------------------------------------------------------------
extern "C" void kernel_launch(void* const* d_in, const int* in_sizes, int n_in,
                              void* d_out, int out_size)
{
    const int*   item_seq   = (const int*)d_in[0];
    const int*   user_ids   = (const int*)d_in[1];
    const int*   items_pred = (const int*)d_in[2];
    const float* user_tab   = (const float*)d_in[3];
    const float* item_tab   = (const float*)d_in[4];
    const float* fiW        = (const float*)d_in[5];
    const float* fib        = (const float*)d_in[6];
    const float* fuW        = (const float*)d_in[7];
    const float* fub        = (const float*)d_in[8];
    const float* gi         = (const float*)d_in[9];
    const float* gu         = (const float*)d_in[10];
    const float* W2         = (const float*)d_in[11];
    const float* b2         = (const float*)d_in[12];
    float*       out        = (float*)d_out;

    const int B = in_sizes[1];  // user_ids element count

    const int pre_grid  = (B + PRE_BPB - 1) / PRE_BPB;
    const int main_grid = (B + BPB - 1) / BPB;

    hgn_pre<<<pre_grid, 128>>>(user_ids, user_tab, fuW, fub, fib, gu, B);
    hgn_main<<<main_grid, 64>>>(item_seq, user_ids, items_pred,
                                user_tab, item_tab, fiW, gi, W2, b2, out, B);
}

// round 4
// speedup vs baseline: 1.2100x; 1.2100x over previous
#include <cuda_runtime.h>
#include <cstdint>

// HGN forward, fused. Shapes fixed: U=I=100000, D=64, L=50, B=4096, T=100.
#define D 64
#define LSEQ 50
#define TPRED 100
#define BPB 2        // batches per block (main kernel)
#define PRE_BPB 16
#define BMAX 4096

__device__ float g_ubias[BMAX * D];    // (u @ fg_user_W) + fg_user_b + fg_item_b
__device__ float g_ugu[BMAX * LSEQ];   // u @ instance_gate_user

static __device__ __forceinline__ unsigned long long pk(float a, float b) {
    unsigned long long r;
    asm("mov.b64 %0, {%1, %2};" : "=l"(r) : "f"(a), "f"(b));
    return r;
}
static __device__ __forceinline__ void upk(unsigned long long v, float& a, float& b) {
    asm("mov.b64 {%0, %1}, %2;" : "=f"(a), "=f"(b) : "l"(v));
}
static __device__ __forceinline__ unsigned long long fma2(
    unsigned long long a, unsigned long long b, unsigned long long c) {
    unsigned long long r;
    asm("fma.rn.f32x2 %0, %1, %2, %3;" : "=l"(r) : "l"(a), "l"(b), "l"(c));
    return r;
}
static __device__ __forceinline__ float sum4(unsigned long long a, unsigned long long b) {
    float a0, a1, b0, b1;
    upk(a, a0, a1); upk(b, b0, b1);
    return (a0 + a1) + (b0 + b1);
}
static __device__ __forceinline__ float sigmoidf(float x) {
    return 1.0f / (1.0f + __expf(-x));
}

// ---------------------------------------------------------------------------
// Precompute: g_ubias[b][d] = u@fg_user_W + fub + fib ; g_ugu[b][l] = u@gu
// ---------------------------------------------------------------------------
__global__ __launch_bounds__(128) void hgn_pre(
    const int* __restrict__ user_ids,
    const float* __restrict__ user_tab,
    const float* __restrict__ fuW,
    const float* __restrict__ fub,
    const float* __restrict__ fib,
    const float* __restrict__ gu,
    int B)
{
    __shared__ __align__(16) float s_u[D];
    const int j = threadIdx.x;

    float wcol[D];
    float biasj = 0.0f;
    if (j < D) {
        #pragma unroll
        for (int k = 0; k < D; k++) wcol[k] = fuW[k * D + j];
        biasj = fub[j] + fib[j];
    } else if (j < D + LSEQ) {
        const int jj = j - D;
        #pragma unroll
        for (int k = 0; k < D; k++) wcol[k] = gu[k * LSEQ + jj];
    }

    const int b0 = blockIdx.x * PRE_BPB;
    for (int bb = 0; bb < PRE_BPB; bb++) {
        const int b = b0 + bb;
        if (b >= B) break;
        if (j < D) {
            const int uid = user_ids[b];
            s_u[j] = user_tab[(size_t)uid * D + j];
        }
        __syncthreads();
        float acc = biasj;
        const float4* up = (const float4*)s_u;
        #pragma unroll
        for (int q = 0; q < D / 4; q++) {
            float4 r = up[q];
            acc += r.x * wcol[4 * q + 0] + r.y * wcol[4 * q + 1]
                 + r.z * wcol[4 * q + 2] + r.w * wcol[4 * q + 3];
        }
        if (j < D)             g_ubias[b * D + j] = acc;
        else if (j < D + LSEQ) g_ugu[b * LSEQ + (j - D)] = acc;
        __syncthreads();
    }
}

// ---------------------------------------------------------------------------
// Main kernel: 128 threads = 2 groups of 64 (grp = tid>>6), 4 warps.
// K-split gating GEMM: group g accumulates k in [32g, 32g+32) with its half
// of the fg_item_W column register-resident (16 x f32x2 = 32 regs).
// ---------------------------------------------------------------------------
__global__ __launch_bounds__(128, 5) void hgn_main(
    const int* __restrict__ item_seq,
    const int* __restrict__ user_ids,
    const int* __restrict__ items_pred,
    const float* __restrict__ user_tab,
    const float* __restrict__ item_tab,
    const float* __restrict__ fiW,
    const float* __restrict__ gi,
    const float* __restrict__ W2,
    const float* __restrict__ b2,
    float* __restrict__ out,
    int B)
{
    __shared__ __align__(16) float s_item[LSEQ][D];
    __shared__ __align__(16) float s_pA[LSEQ][D];     // group-0 partials
    __shared__ __align__(16) float s_gated[LSEQ][D];  // group-1 partials, then gated
    __shared__ __align__(16) float s_v[D];
    __shared__ float s_score[LSEQ];
    __shared__ float s_isum[2][D];
    __shared__ float s_uo[2][D];
    __shared__ float s_ssum[2];
    __shared__ int s_idx[TPRED];
    __shared__ int s_seq[LSEQ];

    const int tid  = threadIdx.x;
    const int d    = tid & 63;
    const int grp  = tid >> 6;      // 0 or 1: K-half owner
    const int lane = tid & 31;
    const int warp = tid >> 5;

    // Half a fg_item_W column: W[32*grp + kk][d], kk=0..31, packed pairs.
    unsigned long long colp[16];
    #pragma unroll
    for (int k = 0; k < 16; k++) {
        float a = fiW[(32 * grp + 2 * k) * D + d];
        float c = fiW[(32 * grp + 2 * k + 1) * D + d];
        colp[k] = pk(a, c);
    }
    const float gi_lo = gi[lane];
    const float gi_hi = gi[lane + 32];

    for (int bb = 0; bb < BPB; bb++) {
        const int b = blockIdx.x * BPB + bb;
        if (b >= B) break;

        // --- stage indices ---
        if (tid < TPRED) s_idx[tid] = items_pred[b * TPRED + tid];
        if (tid < LSEQ)  s_seq[tid] = item_seq[b * LSEQ + tid];
        __syncthreads();

        // --- gather item embeddings, vectorized float4 (800 loads/128 thr) ---
        #pragma unroll
        for (int i = 0; i < 7; i++) {
            const int idx = tid + 128 * i;
            if (idx < LSEQ * (D / 4)) {
                const int l = idx >> 4, q = idx & 15;
                ((float4*)s_item[l])[q] =
                    ((const float4*)(item_tab + (size_t)s_seq[l] * D))[q];
            }
        }
        const float bias = g_ubias[b * D + d];
        const float u    = user_tab[(size_t)user_ids[b] * D + d];
        __syncthreads();

        // --- gating GEMM partials: this group's K-half for all 50 rows,
        //     2 rows per iteration = 4 independent fma2 chains, depth 4 ---
        float (*pout)[D] = grp ? s_gated : s_pA;
        for (int l = 0; l < LSEQ; l += 2) {
            unsigned long long a0 = pk(0.f, 0.f), a1 = pk(0.f, 0.f);
            unsigned long long c0 = pk(0.f, 0.f), c1 = pk(0.f, 0.f);
            const float4* r0 = (const float4*)&s_item[l][grp * 32];
            const float4* r1 = (const float4*)&s_item[l + 1][grp * 32];
            #pragma unroll
            for (int q = 0; q < 8; q++) {
                float4 x = r0[q];
                a0 = fma2(pk(x.x, x.y), colp[2 * q + 0], a0);
                a1 = fma2(pk(x.z, x.w), colp[2 * q + 1], a1);
                float4 y = r1[q];
                c0 = fma2(pk(y.x, y.y), colp[2 * q + 0], c0);
                c1 = fma2(pk(y.z, y.w), colp[2 * q + 1], c1);
            }
            pout[l][d]     = sum4(a0, a1);
            pout[l + 1][d] = sum4(c0, c1);
        }
        __syncthreads();

        // --- combine halves + sigmoid gate; fold item-sum partial ---
        float isum_p = 0.0f;
        {
            const int l0 = grp * 25;
            #pragma unroll 5
            for (int l = l0; l < l0 + 25; l++) {
                const float logit = s_pA[l][d] + s_gated[l][d] + bias;
                const float val   = s_item[l][d];
                s_gated[l][d] = val * sigmoidf(logit);
                isum_p += val;
            }
        }
        s_isum[grp][d] = isum_p;
        __syncthreads();

        // --- instance gating: 4 warps, l strided ---
        for (int l = warp; l < LSEQ; l += 4) {
            float p = s_gated[l][lane] * gi_lo + s_gated[l][lane + 32] * gi_hi;
            p += __shfl_xor_sync(0xffffffffu, p, 16);
            p += __shfl_xor_sync(0xffffffffu, p, 8);
            p += __shfl_xor_sync(0xffffffffu, p, 4);
            p += __shfl_xor_sync(0xffffffffu, p, 2);
            p += __shfl_xor_sync(0xffffffffu, p, 1);
            if (lane == 0) s_score[l] = sigmoidf(p + g_ugu[b * LSEQ + l]);
        }
        __syncthreads();

        // --- union partials over this group's 25 rows ---
        float ssum_p = 0.0f, uo_p = 0.0f;
        {
            const int l0 = grp * 25;
            #pragma unroll 5
            for (int l = l0; l < l0 + 25; l++) {
                const float sc = s_score[l];
                ssum_p += sc;
                uo_p += s_gated[l][d] * sc;
            }
        }
        s_uo[grp][d] = uo_p;
        if (d == 0) s_ssum[grp] = ssum_p;
        __syncthreads();

        if (grp == 0) {
            const float ssum = s_ssum[0] + s_ssum[1];
            s_v[d] = u + s_isum[0][d] + s_isum[1][d]
                   + (s_uo[0][d] + s_uo[1][d]) / ssum;
        }
        __syncthreads();

        // --- scoring: 4 warps x 4 outputs/iter = 16 per iteration ---
        const int g4 = lane >> 3;
        const int gl = lane & 7;
        const float4 va = *(const float4*)&s_v[gl * 8];
        const float4 vb = *(const float4*)&s_v[gl * 8 + 4];
        float* outp = out + (size_t)b * TPRED;
        #pragma unroll
        for (int i = 0; i < 7; i++) {
            const int t = warp * 4 + g4 + 16 * i;
            const int tt = (t < TPRED) ? t : 0;
            const int it = s_idx[tt];
            const float4* rowp = (const float4*)(W2 + (size_t)it * D);
            const float4 a = rowp[gl * 2];
            const float4 c = rowp[gl * 2 + 1];
            float p = a.x * va.x + a.y * va.y + a.z * va.z + a.w * va.w
                    + c.x * vb.x + c.y * vb.y + c.z * vb.z + c.w * vb.w;
            p += __shfl_xor_sync(0xffffffffu, p, 1);
            p += __shfl_xor_sync(0xffffffffu, p, 2);
            p += __shfl_xor_sync(0xffffffffu, p, 4);
            if (t < TPRED && gl == 0) outp[t] = p + b2[it];
        }
        __syncthreads();   // smem reuse for next batch
    }
}

// ---------------------------------------------------------------------------
// Harness entry. Inputs (metadata order):
//  0 item_seq[B,L] i32   1 user_ids[B] i32      2 items_to_predict[B,T] i32
//  3 user_emb[U,D] f32   4 item_emb[I,D] f32
//  5 fg_item_W[D,D]      6 fg_item_b[D]         7 fg_user_W[D,D]   8 fg_user_b[D]
//  9 instance_gate_item[D,1]  10 instance_gate_user[D,L]
// 11 W2_table[I,D]      12 b2_table[I,1]
// Output: res[B,T] f32
// ---------------------------------------------------------------------------
extern "C" void kernel_launch(void* const* d_in, const int* in_sizes, int n_in,
                              void* d_out, int out_size)
{
    const int*   item_seq   = (const int*)d_in[0];
    const int*   user_ids   = (const int*)d_in[1];
    const int*   items_pred = (const int*)d_in[2];
    const float* user_tab   = (const float*)d_in[3];
    const float* item_tab   = (const float*)d_in[4];
    const float* fiW        = (const float*)d_in[5];
    const float* fib        = (const float*)d_in[6];
    const float* fuW        = (const float*)d_in[7];
    const float* fub        = (const float*)d_in[8];
    const float* gi         = (const float*)d_in[9];
    const float* gu         = (const float*)d_in[10];
    const float* W2         = (const float*)d_in[11];
    const float* b2         = (const float*)d_in[12];
    float*       out        = (float*)d_out;

    const int B = in_sizes[1];

    const int pre_grid  = (B + PRE_BPB - 1) / PRE_BPB;
    const int main_grid = (B + BPB - 1) / BPB;

    hgn_pre<<<pre_grid, 128>>>(user_ids, user_tab, fuW, fub, fib, gu, B);
    hgn_main<<<main_grid, 128>>>(item_seq, user_ids, items_pred,
                                 user_tab, item_tab, fiW, gi, W2, b2, out, B);
}